// round 6
// baseline (speedup 1.0000x reference)
#include <cuda_runtime.h>
#include <cuda_fp16.h>
#include <cstdint>

// ---------------- problem constants ----------------
#define NB   2
#define LQ   17821
#define CC   256
#define HD   8
#define LL   4
#define PP   4
#define DD   32
#define LIN  17821
#define MROWS (NB*LQ)      // 35642

__constant__ int c_H[LL]  = {100, 50, 25, 13};
__constant__ int c_W[LL]  = {134, 67, 34, 17};
__constant__ int c_S[LL]  = {0, 13400, 16750, 17600};

// ---------------- scratch ----------------
__device__ __half g_qh [(size_t)MROWS * CC];
__device__ __half g_xh [(size_t)MROWS * CC];
__device__ __half g_wv [256 * 256];
__device__ __half g_wofatt[256 * 384];        // Woff | Watt
__device__ __half g_wout[256 * 256];
__device__ __half g_val [(size_t)MROWS * CC];
__device__ float  g_oa  [(size_t)MROWS * 384]; // off (0-255) | att logits (256-383)
__device__ __half g_core[(size_t)MROWS * CC];

// ---------------- fused fp32->fp16 conversion ----------------
__global__ void convert_all_kernel(
    const float4* __restrict__ xf,   const float4* __restrict__ qf,
    const float4* __restrict__ wvf,  const float4* __restrict__ woutf,
    const float4* __restrict__ wofff,const float4* __restrict__ wattf,
    __half2* __restrict__ xh, __half2* __restrict__ qh,
    __half2* __restrict__ wvh, __half2* __restrict__ wouth,
    __half2* __restrict__ wofatt)
{
    const int i = blockIdx.x * blockDim.x + threadIdx.x;
    const int seg = blockIdx.y;
    auto cvt = [](float4 v, __half2* d) {
        d[0] = __floats2half2_rn(v.x, v.y);
        d[1] = __floats2half2_rn(v.z, v.w);
    };
    if (seg == 0) {
        if (i < MROWS * 64) cvt(xf[i], xh + 2 * i);
    } else if (seg == 1) {
        if (i < MROWS * 64) cvt(qf[i], qh + 2 * i);
    } else if (seg == 2) {
        if (i < 16384) cvt(wvf[i], wvh + 2 * i);
    } else if (seg == 3) {
        if (i < 16384) cvt(woutf[i], wouth + 2 * i);
    } else if (seg == 4) {
        if (i < 16384) {
            int k = i >> 6, j = (i & 63) * 4;
            cvt(wofff[i], wofatt + (k * 384 + j) / 2);
        }
    } else {
        if (i < 8192) {
            int k = i >> 5, j = (i & 31) * 4;
            cvt(wattf[i], wofatt + (k * 384 + 256 + j) / 2);
        }
    }
}

// ================= fp16 tensor-core GEMM core =================
__device__ __forceinline__ int a_swz(int r, int c) {
    return (r * 4 + (c ^ ((r >> 1) & 3))) * 16;
}
__device__ __forceinline__ int b_swz(int r, int c) {
    return (r * 16 + (c ^ (r & 7))) * 16;
}

template <bool HALF_OUT>
__device__ __forceinline__ void hgemm_body(
    int M, int Ncols, int mBase, int nBase,
    const __half* __restrict__ A, const __half* __restrict__ B,
    const float* __restrict__ bp, void* __restrict__ Cv,
    unsigned char* smem_raw)
{
    const int K = 256;
    constexpr int NSTAGE = 3;
    constexpr int STG = 16384;

    const int tid  = threadIdx.x;
    const int lane = tid & 31;
    const int warp = tid >> 5;
    const int wm = warp & 1;
    const int wn = warp >> 1;

    const int rA  = tid >> 1;
    const int cA0 = (tid & 1) * 2;
    const int rB  = tid >> 3;
    const int cB0 = (tid & 7) * 2;
    const int aSz = ((mBase + rA) < M) ? 16 : 0;
    const __half* Ag = A + (size_t)(mBase + rA) * K;
    const __half* Bg = B + nBase;

    const uint32_t smem_base = (uint32_t)__cvta_generic_to_shared(smem_raw);

    float acc[4][4][4];
#pragma unroll
    for (int i = 0; i < 4; i++)
#pragma unroll
        for (int j = 0; j < 4; j++)
#pragma unroll
            for (int c = 0; c < 4; c++) acc[i][j][c] = 0.f;

    auto issue_stage = [&](int kt, int s) {
        const int kb = kt * 32;
        const uint32_t ab = smem_base + s * STG;
        const uint32_t bb = ab + 8192;
#pragma unroll
        for (int c = cA0; c < cA0 + 2; c++) {
            uint32_t d = ab + a_swz(rA, c);
            const void* src = Ag + kb + c * 8;
            asm volatile("cp.async.cg.shared.global [%0], [%1], 16, %2;\n"
                         :: "r"(d), "l"(src), "r"(aSz));
        }
#pragma unroll
        for (int c = cB0; c < cB0 + 2; c++) {
            uint32_t d = bb + b_swz(rB, c);
            const void* src = Bg + (size_t)(kb + rB) * Ncols + c * 8;
            asm volatile("cp.async.cg.shared.global [%0], [%1], 16;\n"
                         :: "r"(d), "l"(src));
        }
        asm volatile("cp.async.commit_group;\n");
    };

    issue_stage(0, 0);
    issue_stage(1, 1);

    const int NKT = K / 32;
    for (int kt = 0; kt < NKT; kt++) {
        const int s = kt % NSTAGE;
        asm volatile("cp.async.wait_group 1;\n");
        __syncthreads();
        const uint32_t ab = smem_base + s * STG;
        const uint32_t bb = ab + 8192;

#pragma unroll
        for (int ks = 0; ks < 2; ks++) {
            uint32_t afr[4][4], bfr[2][4];
#pragma unroll
            for (int i = 0; i < 4; i++) {
                int row = wm * 64 + i * 16 + (lane & 15);
                int c   = 2 * ks + (lane >> 4);
                uint32_t ad = ab + a_swz(row, c);
                asm volatile("ldmatrix.sync.aligned.m8n8.x4.shared.b16 {%0,%1,%2,%3}, [%4];\n"
                             : "=r"(afr[i][0]), "=r"(afr[i][1]), "=r"(afr[i][2]), "=r"(afr[i][3])
                             : "r"(ad));
            }
#pragma unroll
            for (int jj = 0; jj < 2; jj++) {
                int kr = ks * 16 + (lane & 15);
                int c  = wn * 4 + jj * 2 + (lane >> 4);
                uint32_t bd = bb + b_swz(kr, c);
                asm volatile("ldmatrix.sync.aligned.m8n8.x4.trans.shared.b16 {%0,%1,%2,%3}, [%4];\n"
                             : "=r"(bfr[jj][0]), "=r"(bfr[jj][1]), "=r"(bfr[jj][2]), "=r"(bfr[jj][3])
                             : "r"(bd));
            }
#pragma unroll
            for (int i = 0; i < 4; i++)
#pragma unroll
                for (int j = 0; j < 4; j++) {
                    uint32_t b0 = bfr[j >> 1][(j & 1) * 2 + 0];
                    uint32_t b1 = bfr[j >> 1][(j & 1) * 2 + 1];
                    asm volatile(
                        "mma.sync.aligned.m16n8k16.row.col.f32.f16.f16.f32 "
                        "{%0,%1,%2,%3}, {%4,%5,%6,%7}, {%8,%9}, {%0,%1,%2,%3};\n"
                        : "+f"(acc[i][j][0]), "+f"(acc[i][j][1]),
                          "+f"(acc[i][j][2]), "+f"(acc[i][j][3])
                        : "r"(afr[i][0]), "r"(afr[i][1]), "r"(afr[i][2]), "r"(afr[i][3]),
                          "r"(b0), "r"(b1));
                }
        }

        if (kt + 2 < NKT) issue_stage(kt + 2, (kt + 2) % NSTAGE);
        else asm volatile("cp.async.commit_group;\n");
    }

#pragma unroll
    for (int i = 0; i < 4; i++) {
        int r0 = mBase + wm * 64 + i * 16 + (lane >> 2);
        int r1 = r0 + 8;
#pragma unroll
        for (int j = 0; j < 4; j++) {
            int col = nBase + wn * 32 + j * 8 + (lane & 3) * 2;
            float b0 = bp[col], b1 = bp[col + 1];
            float v00 = acc[i][j][0] + b0, v01 = acc[i][j][1] + b1;
            float v10 = acc[i][j][2] + b0, v11 = acc[i][j][3] + b1;
            if (r0 < M) {
                if constexpr (HALF_OUT)
                    *reinterpret_cast<__half2*>((__half*)Cv + (size_t)r0 * Ncols + col) =
                        __floats2half2_rn(v00, v01);
                else
                    *reinterpret_cast<float2*>((float*)Cv + (size_t)r0 * Ncols + col) =
                        make_float2(v00, v01);
            }
            if (r1 < M) {
                if constexpr (HALF_OUT)
                    *reinterpret_cast<__half2*>((__half*)Cv + (size_t)r1 * Ncols + col) =
                        __floats2half2_rn(v10, v11);
                else
                    *reinterpret_cast<float2*>((float*)Cv + (size_t)r1 * Ncols + col) =
                        make_float2(v10, v11);
            }
        }
    }
}

// fused launch: blockIdx.x < 2 -> value GEMM (half out); else -> off|att GEMM (float out)
__global__ __launch_bounds__(256, 3) void hgemm_fused2_kernel(
    const __half* __restrict__ xh, const __half* __restrict__ wv,
    const float*  __restrict__ bv, __half* __restrict__ val,
    const __half* __restrict__ qh, const __half* __restrict__ wofatt,
    const float*  __restrict__ boff, const float* __restrict__ batt,
    float* __restrict__ oa)
{
    __shared__ __align__(16) unsigned char smem_raw[3 * 16384];
    const int bx = blockIdx.x;
    const int mBase = blockIdx.y * 128;
    if (bx < 2) {
        hgemm_body<true>(MROWS, 256, mBase, bx * 128, xh, wv, bv, val, smem_raw);
    } else {
        const int nBase = (bx - 2) * 128;
        const float* bp = (nBase < 256) ? boff : (batt - 256);
        hgemm_body<false>(MROWS, 384, mBase, nBase, qh, wofatt, bp, oa, smem_raw);
    }
}

__global__ __launch_bounds__(256, 3) void hgemm_out_kernel(
    const __half* __restrict__ core, const __half* __restrict__ wout,
    const float* __restrict__ bout, float* __restrict__ out)
{
    __shared__ __align__(16) unsigned char smem_raw[3 * 16384];
    hgemm_body<false>(MROWS, 256, blockIdx.y * 128, blockIdx.x * 128,
                      core, wout, bout, out, smem_raw);
}

// ---------------- sampling: 4 lanes/unit, uint4 gathers, distributed softmax --
__global__ __launch_bounds__(256) void sample_kernel(
    const float* __restrict__ ref,     // (N*LQ, L, 2)
    const float* __restrict__ oa,      // (N*LQ, 384): off | att logits
    const uint4* __restrict__ value,   // (N,Lin,256) halves = 32 uint4/pixel
    uint4*       __restrict__ core)    // (N*LQ, 256) halves = 32 uint4/row
{
    const int t = blockIdx.x * blockDim.x + threadIdx.x;
    const int unit = t >> 2;            // (row, head)
    const int l4   = t & 3;             // lane within unit
    if (unit >= MROWS * HD) return;

    const int lw  = threadIdx.x & 31;   // lane in warp
    const int hd  = unit & (HD - 1);
    const int row = unit >> 3;
    const int n   = (row >= LQ) ? 1 : 0;

    const float* offr = oa + (size_t)row * 384 + hd * 32;
    const float* attr = oa + (size_t)row * 384 + 256 + hd * 16;
    const float* refr = ref + (size_t)row * 8;
    const uint4* vb = value + (size_t)n * (LIN * 32) + hd * 4 + l4;

    // distributed softmax: each of the 4 lanes computes 4 exps, then exchange
    float e[4];
    {
        float4 a4 = *reinterpret_cast<const float4*>(attr + l4 * 4);
        float m = fmaxf(fmaxf(a4.x, a4.y), fmaxf(a4.z, a4.w));
        m = fmaxf(m, __shfl_xor_sync(0xFFFFFFFFu, m, 1));
        m = fmaxf(m, __shfl_xor_sync(0xFFFFFFFFu, m, 2));
        e[0] = __expf(a4.x - m); e[1] = __expf(a4.y - m);
        e[2] = __expf(a4.z - m); e[3] = __expf(a4.w - m);
        float s = e[0] + e[1] + e[2] + e[3];
        s += __shfl_xor_sync(0xFFFFFFFFu, s, 1);
        s += __shfl_xor_sync(0xFFFFFFFFu, s, 2);
        float inv = 1.f / s;
        e[0] *= inv; e[1] *= inv; e[2] *= inv; e[3] *= inv;
    }
    // broadcast all 16 weights to every lane of the unit
    float w[16];
    const int gbase = lw & ~3;
#pragma unroll
    for (int g = 0; g < 4; g++) {
#pragma unroll
        for (int i = 0; i < 4; i++)
            w[g * 4 + i] = __shfl_sync(0xFFFFFFFFu, e[i], gbase | g);
    }

    // offsets (8 x float4, 16B-aligned)
    float4 o4[8];
#pragma unroll
    for (int i = 0; i < 8; i++)
        o4[i] = reinterpret_cast<const float4*>(offr)[i];

    float acc[8];
#pragma unroll
    for (int k = 0; k < 8; k++) acc[k] = 0.f;

#pragma unroll
    for (int l = 0; l < LL; l++) {
        const int H = c_H[l], W = c_W[l];
        const uint4* vlev = vb + (size_t)c_S[l] * 32;
        const float rx = refr[2 * l + 0];
        const float ry = refr[2 * l + 1];
#pragma unroll
        for (int p = 0; p < PP; p++) {
            const int sidx = l * PP + p;
            const float ox = (sidx & 1) ? o4[sidx >> 1].z : o4[sidx >> 1].x;
            const float oy = (sidx & 1) ? o4[sidx >> 1].w : o4[sidx >> 1].y;
            const float aw = w[sidx];
            const float x = rx * (float)W + ox - 0.5f;
            const float y = ry * (float)H + oy - 0.5f;
            const float xf = floorf(x), yf = floorf(y);
            const float fx = x - xf, fy = y - yf;
            const int x0 = (int)xf, y0 = (int)yf;
            const int x1 = x0 + 1,  y1 = y0 + 1;
            const float mx0 = (x0 >= 0 && x0 < W) ? 1.f : 0.f;
            const float mx1 = (x1 >= 0 && x1 < W) ? 1.f : 0.f;
            const float my0 = (y0 >= 0 && y0 < H) ? 1.f : 0.f;
            const float my1 = (y1 >= 0 && y1 < H) ? 1.f : 0.f;
            const int cx0 = min(max(x0, 0), W - 1);
            const int cx1 = min(max(x1, 0), W - 1);
            const int cy0 = min(max(y0, 0), H - 1);
            const int cy1 = min(max(y1, 0), H - 1);
            const float w00 = aw * (1.f - fx) * (1.f - fy) * mx0 * my0;
            const float w10 = aw * fx * (1.f - fy) * mx1 * my0;
            const float w01 = aw * (1.f - fx) * fy * mx0 * my1;
            const float w11 = aw * fx * fy * mx1 * my1;

            const uint4 v00 = vlev[(cy0 * W + cx0) * 32];
            const uint4 v10 = vlev[(cy0 * W + cx1) * 32];
            const uint4 v01 = vlev[(cy1 * W + cx0) * 32];
            const uint4 v11 = vlev[(cy1 * W + cx1) * 32];

            auto fmadd = [&](uint4 v, float wt) {
                float2 a = __half22float2(*reinterpret_cast<const __half2*>(&v.x));
                float2 b = __half22float2(*reinterpret_cast<const __half2*>(&v.y));
                float2 c = __half22float2(*reinterpret_cast<const __half2*>(&v.z));
                float2 d = __half22float2(*reinterpret_cast<const __half2*>(&v.w));
                acc[0] += wt * a.x; acc[1] += wt * a.y;
                acc[2] += wt * b.x; acc[3] += wt * b.y;
                acc[4] += wt * c.x; acc[5] += wt * c.y;
                acc[6] += wt * d.x; acc[7] += wt * d.y;
            };
            fmadd(v00, w00);
            fmadd(v10, w10);
            fmadd(v01, w01);
            fmadd(v11, w11);
        }
    }

    uint4 o;
    *reinterpret_cast<__half2*>(&o.x) = __floats2half2_rn(acc[0], acc[1]);
    *reinterpret_cast<__half2*>(&o.y) = __floats2half2_rn(acc[2], acc[3]);
    *reinterpret_cast<__half2*>(&o.z) = __floats2half2_rn(acc[4], acc[5]);
    *reinterpret_cast<__half2*>(&o.w) = __floats2half2_rn(acc[6], acc[7]);
    core[(size_t)row * 32 + hd * 4 + l4] = o;
}

// ---------------- launch ----------------
extern "C" void kernel_launch(void* const* d_in, const int* in_sizes, int n_in,
                              void* d_out, int out_size)
{
    const float* query = (const float*)d_in[0];
    const float* refpt = (const float*)d_in[1];
    const float* inflt = (const float*)d_in[2];
    const float* Wv    = (const float*)d_in[5];
    const float* bv    = (const float*)d_in[6];
    const float* Woff  = (const float*)d_in[7];
    const float* boff  = (const float*)d_in[8];
    const float* Watt  = (const float*)d_in[9];
    const float* batt  = (const float*)d_in[10];
    const float* Wout  = (const float*)d_in[11];
    const float* bout  = (const float*)d_in[12];
    float* out = (float*)d_out;

    __half *qh, *xh, *wv, *wofatt, *wout, *val, *core;
    float *oa;
    cudaGetSymbolAddress((void**)&qh,     g_qh);
    cudaGetSymbolAddress((void**)&xh,     g_xh);
    cudaGetSymbolAddress((void**)&wv,     g_wv);
    cudaGetSymbolAddress((void**)&wofatt, g_wofatt);
    cudaGetSymbolAddress((void**)&wout,   g_wout);
    cudaGetSymbolAddress((void**)&val,    g_val);
    cudaGetSymbolAddress((void**)&oa,     g_oa);
    cudaGetSymbolAddress((void**)&core,   g_core);

    const int M = MROWS;
    dim3 blk(256);
    const int mb = (M + 127) / 128;   // 279

    // 1. convert everything
    {
        int maxBlocks = (MROWS * 64 + 255) / 256;
        dim3 grid(maxBlocks, 6);
        convert_all_kernel<<<grid, blk>>>(
            (const float4*)inflt, (const float4*)query,
            (const float4*)Wv, (const float4*)Wout,
            (const float4*)Woff, (const float4*)Watt,
            (__half2*)xh, (__half2*)qh, (__half2*)wv, (__half2*)wout,
            (__half2*)wofatt);
    }
    // 2. value GEMM + off|att GEMM fused into one launch
    hgemm_fused2_kernel<<<dim3(5, mb), blk>>>(xh, wv, bv, val,
                                              qh, wofatt, boff, batt, oa);
    // 3. sampling with distributed softmax
    {
        int threads = MROWS * HD * 4;
        sample_kernel<<<(threads + 255) / 256, 256>>>(
            refpt, oa, (const uint4*)val, (uint4*)core);
    }
    // 4. out = core @ Wout + bout
    hgemm_out_kernel<<<dim3(2, mb), blk>>>(core, wout, bout, out);
}

// round 11
// speedup vs baseline: 1.0524x; 1.0524x over previous
#include <cuda_runtime.h>
#include <cuda_fp16.h>
#include <cstdint>

// ---------------- problem constants ----------------
#define NB   2
#define LQ   17821
#define CC   256
#define HD   8
#define LL   4
#define PP   4
#define DD   32
#define LIN  17821
#define MROWS (NB*LQ)      // 35642

__constant__ int c_H[LL]  = {100, 50, 25, 13};
__constant__ int c_W[LL]  = {134, 67, 34, 17};
__constant__ int c_S[LL]  = {0, 13400, 16750, 17600};

// ---------------- scratch ----------------
__device__ __half g_qh [(size_t)MROWS * CC];
__device__ __half g_xh [(size_t)MROWS * CC];
__device__ __half g_wv [256 * 256];
__device__ __half g_wofatt[256 * 384];        // Woff | Watt
__device__ __half g_wout[256 * 256];
// value, head-major: [HD][MROWS][32ch], +32-half pad front and back
__device__ __half g_val [(size_t)MROWS * CC + 64];
__device__ float  g_oa  [(size_t)MROWS * 384]; // off (0-255) | att logits (256-383)
__device__ __half g_core[(size_t)MROWS * CC];

// ---------------- fused fp32->fp16 conversion ----------------
__global__ void convert_all_kernel(
    const float4* __restrict__ xf,   const float4* __restrict__ qf,
    const float4* __restrict__ wvf,  const float4* __restrict__ woutf,
    const float4* __restrict__ wofff,const float4* __restrict__ wattf,
    __half2* __restrict__ xh, __half2* __restrict__ qh,
    __half2* __restrict__ wvh, __half2* __restrict__ wouth,
    __half2* __restrict__ wofatt, __half* __restrict__ valbase)
{
    const int i = blockIdx.x * blockDim.x + threadIdx.x;
    const int seg = blockIdx.y;
    auto cvt = [](float4 v, __half2* d) {
        d[0] = __floats2half2_rn(v.x, v.y);
        d[1] = __floats2half2_rn(v.z, v.w);
    };
    if (seg == 0) {
        if (i < MROWS * 64) cvt(xf[i], xh + 2 * i);
    } else if (seg == 1) {
        if (i < MROWS * 64) cvt(qf[i], qh + 2 * i);
    } else if (seg == 2) {
        if (i < 16384) cvt(wvf[i], wvh + 2 * i);
        if (i < 8) {   // zero the 64B front and back pads of g_val
            reinterpret_cast<uint4*>(valbase)[i & 3] = make_uint4(0, 0, 0, 0);
            reinterpret_cast<uint4*>(valbase + 32 + (size_t)MROWS * CC)[i & 3] =
                make_uint4(0, 0, 0, 0);
        }
    } else if (seg == 3) {
        if (i < 16384) cvt(woutf[i], wouth + 2 * i);
    } else if (seg == 4) {
        if (i < 16384) {
            int k = i >> 6, j = (i & 63) * 4;
            cvt(wofff[i], wofatt + (k * 384 + j) / 2);
        }
    } else {
        if (i < 8192) {
            int k = i >> 5, j = (i & 31) * 4;
            cvt(wattf[i], wofatt + (k * 384 + 256 + j) / 2);
        }
    }
}

// ================= fp16 tensor-core GEMM core =================
__device__ __forceinline__ int a_swz(int r, int c) {
    return (r * 4 + (c ^ ((r >> 1) & 3))) * 16;
}
__device__ __forceinline__ int b_swz(int r, int c) {
    return (r * 16 + (c ^ (r & 7))) * 16;
}

// OMODE: 0 = float row-major, 1 = half head-major (value layout)
template <int OMODE>
__device__ __forceinline__ void hgemm_body(
    int M, int Ncols, int mBase, int nBase,
    const __half* __restrict__ A, const __half* __restrict__ B,
    const float* __restrict__ bp, void* __restrict__ Cv,
    unsigned char* smem_raw)
{
    const int K = 256;
    constexpr int NSTAGE = 3;
    constexpr int STG = 16384;

    const int tid  = threadIdx.x;
    const int lane = tid & 31;
    const int warp = tid >> 5;
    const int wm = warp & 1;
    const int wn = warp >> 1;

    const int rA  = tid >> 1;
    const int cA0 = (tid & 1) * 2;
    const int rB  = tid >> 3;
    const int cB0 = (tid & 7) * 2;
    const int aSz = ((mBase + rA) < M) ? 16 : 0;
    const __half* Ag = A + (size_t)(mBase + rA) * K;
    const __half* Bg = B + nBase;

    const uint32_t smem_base = (uint32_t)__cvta_generic_to_shared(smem_raw);

    float acc[4][4][4];
#pragma unroll
    for (int i = 0; i < 4; i++)
#pragma unroll
        for (int j = 0; j < 4; j++)
#pragma unroll
            for (int c = 0; c < 4; c++) acc[i][j][c] = 0.f;

    auto issue_stage = [&](int kt, int s) {
        const int kb = kt * 32;
        const uint32_t ab = smem_base + s * STG;
        const uint32_t bb = ab + 8192;
#pragma unroll
        for (int c = cA0; c < cA0 + 2; c++) {
            uint32_t d = ab + a_swz(rA, c);
            const void* src = Ag + kb + c * 8;
            asm volatile("cp.async.cg.shared.global [%0], [%1], 16, %2;\n"
                         :: "r"(d), "l"(src), "r"(aSz));
        }
#pragma unroll
        for (int c = cB0; c < cB0 + 2; c++) {
            uint32_t d = bb + b_swz(rB, c);
            const void* src = Bg + (size_t)(kb + rB) * Ncols + c * 8;
            asm volatile("cp.async.cg.shared.global [%0], [%1], 16;\n"
                         :: "r"(d), "l"(src));
        }
        asm volatile("cp.async.commit_group;\n");
    };

    issue_stage(0, 0);
    issue_stage(1, 1);

    const int NKT = K / 32;
    for (int kt = 0; kt < NKT; kt++) {
        const int s = kt % NSTAGE;
        asm volatile("cp.async.wait_group 1;\n");
        __syncthreads();
        const uint32_t ab = smem_base + s * STG;
        const uint32_t bb = ab + 8192;

#pragma unroll
        for (int ks = 0; ks < 2; ks++) {
            uint32_t afr[4][4], bfr[2][4];
#pragma unroll
            for (int i = 0; i < 4; i++) {
                int row = wm * 64 + i * 16 + (lane & 15);
                int c   = 2 * ks + (lane >> 4);
                uint32_t ad = ab + a_swz(row, c);
                asm volatile("ldmatrix.sync.aligned.m8n8.x4.shared.b16 {%0,%1,%2,%3}, [%4];\n"
                             : "=r"(afr[i][0]), "=r"(afr[i][1]), "=r"(afr[i][2]), "=r"(afr[i][3])
                             : "r"(ad));
            }
#pragma unroll
            for (int jj = 0; jj < 2; jj++) {
                int kr = ks * 16 + (lane & 15);
                int c  = wn * 4 + jj * 2 + (lane >> 4);
                uint32_t bd = bb + b_swz(kr, c);
                asm volatile("ldmatrix.sync.aligned.m8n8.x4.trans.shared.b16 {%0,%1,%2,%3}, [%4];\n"
                             : "=r"(bfr[jj][0]), "=r"(bfr[jj][1]), "=r"(bfr[jj][2]), "=r"(bfr[jj][3])
                             : "r"(bd));
            }
#pragma unroll
            for (int i = 0; i < 4; i++)
#pragma unroll
                for (int j = 0; j < 4; j++) {
                    uint32_t b0 = bfr[j >> 1][(j & 1) * 2 + 0];
                    uint32_t b1 = bfr[j >> 1][(j & 1) * 2 + 1];
                    asm volatile(
                        "mma.sync.aligned.m16n8k16.row.col.f32.f16.f16.f32 "
                        "{%0,%1,%2,%3}, {%4,%5,%6,%7}, {%8,%9}, {%0,%1,%2,%3};\n"
                        : "+f"(acc[i][j][0]), "+f"(acc[i][j][1]),
                          "+f"(acc[i][j][2]), "+f"(acc[i][j][3])
                        : "r"(afr[i][0]), "r"(afr[i][1]), "r"(afr[i][2]), "r"(afr[i][3]),
                          "r"(b0), "r"(b1));
                }
        }

        if (kt + 2 < NKT) issue_stage(kt + 2, (kt + 2) % NSTAGE);
        else asm volatile("cp.async.commit_group;\n");
    }

#pragma unroll
    for (int i = 0; i < 4; i++) {
        int r0 = mBase + wm * 64 + i * 16 + (lane >> 2);
        int r1 = r0 + 8;
#pragma unroll
        for (int j = 0; j < 4; j++) {
            int col = nBase + wn * 32 + j * 8 + (lane & 3) * 2;
            float b0 = bp[col], b1 = bp[col + 1];
            float v00 = acc[i][j][0] + b0, v01 = acc[i][j][1] + b1;
            float v10 = acc[i][j][2] + b0, v11 = acc[i][j][3] + b1;
            if constexpr (OMODE == 1) {
                // head-major: [head=col>>5][row][ch=col&31]
                __half* V = (__half*)Cv;
                size_t base = (size_t)(col >> 5) * ((size_t)MROWS * 32) + (col & 31);
                if (r0 < M)
                    *reinterpret_cast<__half2*>(V + base + (size_t)r0 * 32) =
                        __floats2half2_rn(v00, v01);
                if (r1 < M)
                    *reinterpret_cast<__half2*>(V + base + (size_t)r1 * 32) =
                        __floats2half2_rn(v10, v11);
            } else {
                float* F = (float*)Cv;
                if (r0 < M)
                    *reinterpret_cast<float2*>(F + (size_t)r0 * Ncols + col) =
                        make_float2(v00, v01);
                if (r1 < M)
                    *reinterpret_cast<float2*>(F + (size_t)r1 * Ncols + col) =
                        make_float2(v10, v11);
            }
        }
    }
}

// fused launch: blockIdx.x < 2 -> value GEMM (head-major half); else -> off|att GEMM
__global__ __launch_bounds__(256) void hgemm_fused2_kernel(
    const __half* __restrict__ xh, const __half* __restrict__ wv,
    const float*  __restrict__ bv, __half* __restrict__ val,
    const __half* __restrict__ qh, const __half* __restrict__ wofatt,
    const float*  __restrict__ boff, const float* __restrict__ batt,
    float* __restrict__ oa)
{
    __shared__ __align__(16) unsigned char smem_raw[3 * 16384];
    const int bx = blockIdx.x;
    const int mBase = blockIdx.y * 128;
    if (bx < 2) {
        hgemm_body<1>(MROWS, 256, mBase, bx * 128, xh, wv, bv, val, smem_raw);
    } else {
        const int nBase = (bx - 2) * 128;
        const float* bp = (nBase < 256) ? boff : (batt - 256);
        hgemm_body<0>(MROWS, 384, mBase, nBase, qh, wofatt, bp, oa, smem_raw);
    }
}

__global__ __launch_bounds__(256) void hgemm_out_kernel(
    const __half* __restrict__ core, const __half* __restrict__ wout,
    const float* __restrict__ bout, float* __restrict__ out)
{
    __shared__ __align__(16) unsigned char smem_raw[3 * 16384];
    hgemm_body<0>(MROWS, 256, blockIdx.y * 128, blockIdx.x * 128,
                  core, wout, bout, out, smem_raw);
}

// ---------------- sampling: 8 lanes/unit, 128B x-span gathers ----------------
// value head-major [HD][MROWS][32ch]; lanes 0-3 = x0 channels, 4-7 = x1 channels
__global__ __launch_bounds__(256) void sample_kernel(
    const float* __restrict__ ref,     // (N*LQ, L, 2)
    const float* __restrict__ oa,      // (N*LQ, 384): off | att logits
    const uint4* __restrict__ value,   // head-major, past front pad; 4 uint4/pixel
    uint4*       __restrict__ core)    // (N*LQ, 256) halves = 32 uint4/row
{
    const int t = blockIdx.x * blockDim.x + threadIdx.x;
    const int unit  = t >> 3;           // (row, head)
    const int lane8 = t & 7;
    if (unit >= MROWS * HD) return;

    const int lw  = threadIdx.x & 31;
    const int hd  = unit & (HD - 1);
    const int row = unit >> 3;
    const int n   = (row >= LQ) ? 1 : 0;

    const float* offr = oa + (size_t)row * 384 + hd * 32;
    const float* attr = oa + (size_t)row * 384 + 256 + hd * 16;
    const float* refr = ref + (size_t)row * 8;
    // base for this (n, head): uint4 units; lane8 picks 16B within the 128B span
    const uint4* vb = value + (size_t)hd * (MROWS * 4) + (size_t)n * (LIN * 4) + lane8;

    // distributed softmax: 2 logits per lane across the 8-lane unit
    float e0, e1;
    {
        float2 a2 = *reinterpret_cast<const float2*>(attr + lane8 * 2);
        float m = fmaxf(a2.x, a2.y);
        m = fmaxf(m, __shfl_xor_sync(0xFFFFFFFFu, m, 1));
        m = fmaxf(m, __shfl_xor_sync(0xFFFFFFFFu, m, 2));
        m = fmaxf(m, __shfl_xor_sync(0xFFFFFFFFu, m, 4));
        e0 = __expf(a2.x - m);
        e1 = __expf(a2.y - m);
        float s = e0 + e1;
        s += __shfl_xor_sync(0xFFFFFFFFu, s, 1);
        s += __shfl_xor_sync(0xFFFFFFFFu, s, 2);
        s += __shfl_xor_sync(0xFFFFFFFFu, s, 4);
        float inv = 1.f / s;
        e0 *= inv; e1 *= inv;
    }
    float w[16];
    const int gbase = lw & ~7;
#pragma unroll
    for (int g = 0; g < 8; g++) {
        w[g * 2 + 0] = __shfl_sync(0xFFFFFFFFu, e0, gbase | g);
        w[g * 2 + 1] = __shfl_sync(0xFFFFFFFFu, e1, gbase | g);
    }

    // offsets (same addresses across lanes -> L1 broadcast)
    float4 o4[8];
#pragma unroll
    for (int i = 0; i < 8; i++)
        o4[i] = reinterpret_cast<const float4*>(offr)[i];

    const float isx1 = (lane8 >= 4) ? 1.f : 0.f;

    float acc[8];
#pragma unroll
    for (int k = 0; k < 8; k++) acc[k] = 0.f;

#pragma unroll
    for (int l = 0; l < LL; l++) {
        const int H = c_H[l], W = c_W[l];
        const uint4* vlev = vb + (size_t)c_S[l] * 4;
        const float rx = refr[2 * l + 0];
        const float ry = refr[2 * l + 1];
#pragma unroll
        for (int p = 0; p < PP; p++) {
            const int sidx = l * PP + p;
            const float ox = (sidx & 1) ? o4[sidx >> 1].z : o4[sidx >> 1].x;
            const float oy = (sidx & 1) ? o4[sidx >> 1].w : o4[sidx >> 1].y;
            const float aw = w[sidx];
            const float x = rx * (float)W + ox - 0.5f;
            const float y = ry * (float)H + oy - 0.5f;
            const float xf = floorf(x), yf = floorf(y);
            const float fx = x - xf, fy = y - yf;
            const int x0 = (int)xf, y0 = (int)yf;
            const int y1 = y0 + 1;
            // per-lane x weight: lanes 0-3 get x0's, 4-7 get x1's
            const float mx0 = (x0 >= 0 && x0 < W) ? 1.f : 0.f;
            const float mx1 = (x0 >= -1 && x0 < W - 1) ? 1.f : 0.f;
            const float wx = isx1 ? (fx * mx1) : ((1.f - fx) * mx0);
            const float my0 = (y0 >= 0 && y0 < H) ? 1.f : 0.f;
            const float my1 = (y1 >= 0 && y1 < H) ? 1.f : 0.f;
            const int cxb = min(max(x0, -1), W - 1);  // span base (can be -1: front pad)
            const int cy0 = min(max(y0, 0), H - 1);
            const int cy1 = min(max(y1, 0), H - 1);
            const float w0 = aw * (1.f - fy) * my0 * wx;
            const float w1 = aw * fy * my1 * wx;

            const uint4 v0 = vlev[(cy0 * W + cxb) * 4];
            const uint4 v1 = vlev[(cy1 * W + cxb) * 4];

            auto fmadd = [&](uint4 v, float wt) {
                float2 a = __half22float2(*reinterpret_cast<const __half2*>(&v.x));
                float2 b = __half22float2(*reinterpret_cast<const __half2*>(&v.y));
                float2 c = __half22float2(*reinterpret_cast<const __half2*>(&v.z));
                float2 d = __half22float2(*reinterpret_cast<const __half2*>(&v.w));
                acc[0] += wt * a.x; acc[1] += wt * a.y;
                acc[2] += wt * b.x; acc[3] += wt * b.y;
                acc[4] += wt * c.x; acc[5] += wt * c.y;
                acc[6] += wt * d.x; acc[7] += wt * d.y;
            };
            fmadd(v0, w0);
            fmadd(v1, w1);
        }
    }

    // fold x1 half into x0 half (lanes l and l^4 hold identical channel sets)
#pragma unroll
    for (int k = 0; k < 8; k++)
        acc[k] += __shfl_xor_sync(0xFFFFFFFFu, acc[k], 4);

    if (lane8 < 4) {
        uint4 o;
        *reinterpret_cast<__half2*>(&o.x) = __floats2half2_rn(acc[0], acc[1]);
        *reinterpret_cast<__half2*>(&o.y) = __floats2half2_rn(acc[2], acc[3]);
        *reinterpret_cast<__half2*>(&o.z) = __floats2half2_rn(acc[4], acc[5]);
        *reinterpret_cast<__half2*>(&o.w) = __floats2half2_rn(acc[6], acc[7]);
        core[(size_t)row * 32 + hd * 4 + lane8] = o;
    }
}

// ---------------- launch ----------------
extern "C" void kernel_launch(void* const* d_in, const int* in_sizes, int n_in,
                              void* d_out, int out_size)
{
    const float* query = (const float*)d_in[0];
    const float* refpt = (const float*)d_in[1];
    const float* inflt = (const float*)d_in[2];
    const float* Wv    = (const float*)d_in[5];
    const float* bv    = (const float*)d_in[6];
    const float* Woff  = (const float*)d_in[7];
    const float* boff  = (const float*)d_in[8];
    const float* Watt  = (const float*)d_in[9];
    const float* batt  = (const float*)d_in[10];
    const float* Wout  = (const float*)d_in[11];
    const float* bout  = (const float*)d_in[12];
    float* out = (float*)d_out;

    __half *qh, *xh, *wv, *wofatt, *wout, *valbase, *core;
    float *oa;
    cudaGetSymbolAddress((void**)&qh,      g_qh);
    cudaGetSymbolAddress((void**)&xh,      g_xh);
    cudaGetSymbolAddress((void**)&wv,      g_wv);
    cudaGetSymbolAddress((void**)&wofatt,  g_wofatt);
    cudaGetSymbolAddress((void**)&wout,    g_wout);
    cudaGetSymbolAddress((void**)&valbase, g_val);
    cudaGetSymbolAddress((void**)&oa,      g_oa);
    cudaGetSymbolAddress((void**)&core,    g_core);
    __half* val = valbase + 32;   // past 64B front pad

    const int M = MROWS;
    dim3 blk(256);
    const int mb = (M + 127) / 128;   // 279

    // 1. convert everything (+ zero value pads)
    {
        int maxBlocks = (MROWS * 64 + 255) / 256;
        dim3 grid(maxBlocks, 6);
        convert_all_kernel<<<grid, blk>>>(
            (const float4*)inflt, (const float4*)query,
            (const float4*)Wv, (const float4*)Wout,
            (const float4*)Woff, (const float4*)Watt,
            (__half2*)xh, (__half2*)qh, (__half2*)wv, (__half2*)wout,
            (__half2*)wofatt, valbase);
    }
    // 2. value GEMM (head-major out) + off|att GEMM, one launch
    hgemm_fused2_kernel<<<dim3(5, mb), blk>>>(xh, wv, bv, val,
                                              qh, wofatt, boff, batt, oa);
    // 3. sampling (8 lanes/unit, 128B spans, distributed softmax)
    {
        long long threads = (long long)MROWS * HD * 8;
        int blocks = (int)((threads + 255) / 256);
        sample_kernel<<<blocks, 256>>>(
            refpt, oa, (const uint4*)val, (uint4*)core);
    }
    // 4. out = core @ Wout + bout
    hgemm_out_kernel<<<dim3(2, mb), blk>>>(core, wout, bout, out);
}

// round 12
// speedup vs baseline: 1.0906x; 1.0364x over previous
#include <cuda_runtime.h>
#include <cuda_fp16.h>
#include <cstdint>

// ---------------- problem constants ----------------
#define NB   2
#define LQ   17821
#define CC   256
#define HD   8
#define LL   4
#define PP   4
#define DD   32
#define LIN  17821
#define MROWS (NB*LQ)      // 35642

__constant__ int c_H[LL]  = {100, 50, 25, 13};
__constant__ int c_W[LL]  = {134, 67, 34, 17};
__constant__ int c_S[LL]  = {0, 13400, 16750, 17600};

// ---------------- scratch ----------------
__device__ __half g_qh [(size_t)MROWS * CC];
__device__ __half g_xh [(size_t)MROWS * CC];
__device__ __half g_wv [256 * 256];
__device__ __half g_wofatt[256 * 384];        // Woff | Watt
__device__ __half g_wout[256 * 256];
__device__ __half g_val [(size_t)MROWS * CC];
__device__ float  g_oa  [(size_t)MROWS * 384]; // off (0-255) | att logits (256-383)
__device__ __half g_core[(size_t)MROWS * CC];

// ---------------- fused fp32->fp16 conversion ----------------
__global__ void convert_all_kernel(
    const float4* __restrict__ xf,   const float4* __restrict__ qf,
    const float4* __restrict__ wvf,  const float4* __restrict__ woutf,
    const float4* __restrict__ wofff,const float4* __restrict__ wattf,
    __half2* __restrict__ xh, __half2* __restrict__ qh,
    __half2* __restrict__ wvh, __half2* __restrict__ wouth,
    __half2* __restrict__ wofatt)
{
    const int i = blockIdx.x * blockDim.x + threadIdx.x;
    const int seg = blockIdx.y;
    auto cvt = [](float4 v, __half2* d) {
        d[0] = __floats2half2_rn(v.x, v.y);
        d[1] = __floats2half2_rn(v.z, v.w);
    };
    if (seg == 0) {
        if (i < MROWS * 64) cvt(xf[i], xh + 2 * i);
    } else if (seg == 1) {
        if (i < MROWS * 64) cvt(qf[i], qh + 2 * i);
    } else if (seg == 2) {
        if (i < 16384) cvt(wvf[i], wvh + 2 * i);
    } else if (seg == 3) {
        if (i < 16384) cvt(woutf[i], wouth + 2 * i);
    } else if (seg == 4) {
        if (i < 16384) {
            int k = i >> 6, j = (i & 63) * 4;
            cvt(wofff[i], wofatt + (k * 384 + j) / 2);
        }
    } else {
        if (i < 8192) {
            int k = i >> 5, j = (i & 31) * 4;
            cvt(wattf[i], wofatt + (k * 384 + 256 + j) / 2);
        }
    }
}

// ================= fp16 tensor-core GEMM core =================
// 5-stage cp.async pipeline in dynamic smem (80KB), wait_group 3.
#define NSTAGE 5
#define STG    16384

__device__ __forceinline__ int a_swz(int r, int c) {
    return (r * 4 + (c ^ ((r >> 1) & 3))) * 16;
}
__device__ __forceinline__ int b_swz(int r, int c) {
    return (r * 16 + (c ^ (r & 7))) * 16;
}

template <bool HALF_OUT>
__device__ __forceinline__ void hgemm_body(
    int M, int Ncols, int mBase, int nBase,
    const __half* __restrict__ A, const __half* __restrict__ B,
    const float* __restrict__ bp, void* __restrict__ Cv,
    unsigned char* smem_raw)
{
    const int K = 256;

    const int tid  = threadIdx.x;
    const int lane = tid & 31;
    const int warp = tid >> 5;
    const int wm = warp & 1;
    const int wn = warp >> 1;

    const int rA  = tid >> 1;
    const int cA0 = (tid & 1) * 2;
    const int rB  = tid >> 3;
    const int cB0 = (tid & 7) * 2;
    const int aSz = ((mBase + rA) < M) ? 16 : 0;
    const __half* Ag = A + (size_t)(mBase + rA) * K;
    const __half* Bg = B + nBase;

    const uint32_t smem_base = (uint32_t)__cvta_generic_to_shared(smem_raw);

    float acc[4][4][4];
#pragma unroll
    for (int i = 0; i < 4; i++)
#pragma unroll
        for (int j = 0; j < 4; j++)
#pragma unroll
            for (int c = 0; c < 4; c++) acc[i][j][c] = 0.f;

    auto issue_stage = [&](int kt, int s) {
        const int kb = kt * 32;
        const uint32_t ab = smem_base + s * STG;
        const uint32_t bb = ab + 8192;
#pragma unroll
        for (int c = cA0; c < cA0 + 2; c++) {
            uint32_t d = ab + a_swz(rA, c);
            const void* src = Ag + kb + c * 8;
            asm volatile("cp.async.cg.shared.global [%0], [%1], 16, %2;\n"
                         :: "r"(d), "l"(src), "r"(aSz));
        }
#pragma unroll
        for (int c = cB0; c < cB0 + 2; c++) {
            uint32_t d = bb + b_swz(rB, c);
            const void* src = Bg + (size_t)(kb + rB) * Ncols + c * 8;
            asm volatile("cp.async.cg.shared.global [%0], [%1], 16;\n"
                         :: "r"(d), "l"(src));
        }
        asm volatile("cp.async.commit_group;\n");
    };

    issue_stage(0, 0);
    issue_stage(1, 1);
    issue_stage(2, 2);
    issue_stage(3, 3);

    const int NKT = K / 32;   // 8
    for (int kt = 0; kt < NKT; kt++) {
        const int s = kt % NSTAGE;
        asm volatile("cp.async.wait_group 3;\n");
        __syncthreads();
        const uint32_t ab = smem_base + s * STG;
        const uint32_t bb = ab + 8192;

#pragma unroll
        for (int ks = 0; ks < 2; ks++) {
            uint32_t afr[4][4], bfr[2][4];
#pragma unroll
            for (int i = 0; i < 4; i++) {
                int row = wm * 64 + i * 16 + (lane & 15);
                int c   = 2 * ks + (lane >> 4);
                uint32_t ad = ab + a_swz(row, c);
                asm volatile("ldmatrix.sync.aligned.m8n8.x4.shared.b16 {%0,%1,%2,%3}, [%4];\n"
                             : "=r"(afr[i][0]), "=r"(afr[i][1]), "=r"(afr[i][2]), "=r"(afr[i][3])
                             : "r"(ad));
            }
#pragma unroll
            for (int jj = 0; jj < 2; jj++) {
                int kr = ks * 16 + (lane & 15);
                int c  = wn * 4 + jj * 2 + (lane >> 4);
                uint32_t bd = bb + b_swz(kr, c);
                asm volatile("ldmatrix.sync.aligned.m8n8.x4.trans.shared.b16 {%0,%1,%2,%3}, [%4];\n"
                             : "=r"(bfr[jj][0]), "=r"(bfr[jj][1]), "=r"(bfr[jj][2]), "=r"(bfr[jj][3])
                             : "r"(bd));
            }
#pragma unroll
            for (int i = 0; i < 4; i++)
#pragma unroll
                for (int j = 0; j < 4; j++) {
                    uint32_t b0 = bfr[j >> 1][(j & 1) * 2 + 0];
                    uint32_t b1 = bfr[j >> 1][(j & 1) * 2 + 1];
                    asm volatile(
                        "mma.sync.aligned.m16n8k16.row.col.f32.f16.f16.f32 "
                        "{%0,%1,%2,%3}, {%4,%5,%6,%7}, {%8,%9}, {%0,%1,%2,%3};\n"
                        : "+f"(acc[i][j][0]), "+f"(acc[i][j][1]),
                          "+f"(acc[i][j][2]), "+f"(acc[i][j][3])
                        : "r"(afr[i][0]), "r"(afr[i][1]), "r"(afr[i][2]), "r"(afr[i][3]),
                          "r"(b0), "r"(b1));
                }
        }

        if (kt + 4 < NKT) issue_stage(kt + 4, (kt + 4) % NSTAGE);
        else asm volatile("cp.async.commit_group;\n");
    }

#pragma unroll
    for (int i = 0; i < 4; i++) {
        int r0 = mBase + wm * 64 + i * 16 + (lane >> 2);
        int r1 = r0 + 8;
#pragma unroll
        for (int j = 0; j < 4; j++) {
            int col = nBase + wn * 32 + j * 8 + (lane & 3) * 2;
            float b0 = bp[col], b1 = bp[col + 1];
            float v00 = acc[i][j][0] + b0, v01 = acc[i][j][1] + b1;
            float v10 = acc[i][j][2] + b0, v11 = acc[i][j][3] + b1;
            if (r0 < M) {
                if constexpr (HALF_OUT)
                    *reinterpret_cast<__half2*>((__half*)Cv + (size_t)r0 * Ncols + col) =
                        __floats2half2_rn(v00, v01);
                else
                    *reinterpret_cast<float2*>((float*)Cv + (size_t)r0 * Ncols + col) =
                        make_float2(v00, v01);
            }
            if (r1 < M) {
                if constexpr (HALF_OUT)
                    *reinterpret_cast<__half2*>((__half*)Cv + (size_t)r1 * Ncols + col) =
                        __floats2half2_rn(v10, v11);
                else
                    *reinterpret_cast<float2*>((float*)Cv + (size_t)r1 * Ncols + col) =
                        make_float2(v10, v11);
            }
        }
    }
}

// fused launch: blockIdx.x < 2 -> value GEMM (half out); else -> off|att GEMM (float out)
__global__ __launch_bounds__(256) void hgemm_fused2_kernel(
    const __half* __restrict__ xh, const __half* __restrict__ wv,
    const float*  __restrict__ bv, __half* __restrict__ val,
    const __half* __restrict__ qh, const __half* __restrict__ wofatt,
    const float*  __restrict__ boff, const float* __restrict__ batt,
    float* __restrict__ oa)
{
    extern __shared__ __align__(16) unsigned char smem_raw[];
    const int bx = blockIdx.x;
    const int mBase = blockIdx.y * 128;
    if (bx < 2) {
        hgemm_body<true>(MROWS, 256, mBase, bx * 128, xh, wv, bv, val, smem_raw);
    } else {
        const int nBase = (bx - 2) * 128;
        const float* bp = (nBase < 256) ? boff : (batt - 256);
        hgemm_body<false>(MROWS, 384, mBase, nBase, qh, wofatt, bp, oa, smem_raw);
    }
}

__global__ __launch_bounds__(256) void hgemm_out_kernel(
    const __half* __restrict__ core, const __half* __restrict__ wout,
    const float* __restrict__ bout, float* __restrict__ out)
{
    extern __shared__ __align__(16) unsigned char smem_raw[];
    hgemm_body<false>(MROWS, 256, blockIdx.y * 128, blockIdx.x * 128,
                      core, wout, bout, out, smem_raw);
}

// ---------------- sampling: 4 lanes/unit, uint4 gathers, fused softmax -------
__global__ __launch_bounds__(256) void sample_kernel(
    const float* __restrict__ ref,     // (N*LQ, L, 2)
    const float* __restrict__ oa,      // (N*LQ, 384): off | att logits
    const uint4* __restrict__ value,   // (N,Lin,256) halves = 32 uint4/pixel
    uint4*       __restrict__ core)    // (N*LQ, 256) halves = 32 uint4/row
{
    const int t = blockIdx.x * blockDim.x + threadIdx.x;
    const int unit = t >> 2;            // (row, head)
    const int l4   = t & 3;             // lane within unit: channels [l4*8, l4*8+8)
    if (unit >= MROWS * HD) return;

    const int hd  = unit & (HD - 1);
    const int row = unit >> 3;
    const int n   = (row >= LQ) ? 1 : 0;

    const float* offr = oa + (size_t)row * 384 + hd * 32;
    const float* attr = oa + (size_t)row * 384 + 256 + hd * 16;
    const float* refr = ref + (size_t)row * 8;
    const uint4* vb = value + (size_t)n * (LIN * 32) + hd * 4 + l4;

    // inline softmax over the unit's 16 logits
    float w[16];
    float m = -1e30f;
#pragma unroll
    for (int i = 0; i < 16; i++) { w[i] = attr[i]; m = fmaxf(m, w[i]); }
    float s = 0.f;
#pragma unroll
    for (int i = 0; i < 16; i++) { w[i] = __expf(w[i] - m); s += w[i]; }
    const float inv = 1.f / s;

    float acc[8];
#pragma unroll
    for (int k = 0; k < 8; k++) acc[k] = 0.f;

#pragma unroll
    for (int l = 0; l < LL; l++) {
        const int H = c_H[l], W = c_W[l];
        const uint4* vlev = vb + (size_t)c_S[l] * 32;
        const float rx = refr[2 * l + 0];
        const float ry = refr[2 * l + 1];
#pragma unroll
        for (int p = 0; p < PP; p++) {
            const float ox = offr[(l * PP + p) * 2 + 0];
            const float oy = offr[(l * PP + p) * 2 + 1];
            const float aw = w[l * PP + p] * inv;
            const float x = rx * (float)W + ox - 0.5f;
            const float y = ry * (float)H + oy - 0.5f;
            const float xf = floorf(x), yf = floorf(y);
            const float fx = x - xf, fy = y - yf;
            const int x0 = (int)xf, y0 = (int)yf;
            const int x1 = x0 + 1,  y1 = y0 + 1;
            const float mx0 = (x0 >= 0 && x0 < W) ? 1.f : 0.f;
            const float mx1 = (x1 >= 0 && x1 < W) ? 1.f : 0.f;
            const float my0 = (y0 >= 0 && y0 < H) ? 1.f : 0.f;
            const float my1 = (y1 >= 0 && y1 < H) ? 1.f : 0.f;
            const int cx0 = min(max(x0, 0), W - 1);
            const int cx1 = min(max(x1, 0), W - 1);
            const int cy0 = min(max(y0, 0), H - 1);
            const int cy1 = min(max(y1, 0), H - 1);
            const float w00 = aw * (1.f - fx) * (1.f - fy) * mx0 * my0;
            const float w10 = aw * fx * (1.f - fy) * mx1 * my0;
            const float w01 = aw * (1.f - fx) * fy * mx0 * my1;
            const float w11 = aw * fx * fy * mx1 * my1;

            const uint4 v00 = vlev[(cy0 * W + cx0) * 32];
            const uint4 v10 = vlev[(cy0 * W + cx1) * 32];
            const uint4 v01 = vlev[(cy1 * W + cx0) * 32];
            const uint4 v11 = vlev[(cy1 * W + cx1) * 32];

            auto fmadd = [&](uint4 v, float wt) {
                float2 a = __half22float2(*reinterpret_cast<const __half2*>(&v.x));
                float2 b = __half22float2(*reinterpret_cast<const __half2*>(&v.y));
                float2 c = __half22float2(*reinterpret_cast<const __half2*>(&v.z));
                float2 d = __half22float2(*reinterpret_cast<const __half2*>(&v.w));
                acc[0] += wt * a.x; acc[1] += wt * a.y;
                acc[2] += wt * b.x; acc[3] += wt * b.y;
                acc[4] += wt * c.x; acc[5] += wt * c.y;
                acc[6] += wt * d.x; acc[7] += wt * d.y;
            };
            fmadd(v00, w00);
            fmadd(v10, w10);
            fmadd(v01, w01);
            fmadd(v11, w11);
        }
    }

    uint4 o;
    *reinterpret_cast<__half2*>(&o.x) = __floats2half2_rn(acc[0], acc[1]);
    *reinterpret_cast<__half2*>(&o.y) = __floats2half2_rn(acc[2], acc[3]);
    *reinterpret_cast<__half2*>(&o.z) = __floats2half2_rn(acc[4], acc[5]);
    *reinterpret_cast<__half2*>(&o.w) = __floats2half2_rn(acc[6], acc[7]);
    core[(size_t)row * 32 + hd * 4 + l4] = o;
}

// ---------------- launch ----------------
extern "C" void kernel_launch(void* const* d_in, const int* in_sizes, int n_in,
                              void* d_out, int out_size)
{
    const float* query = (const float*)d_in[0];
    const float* refpt = (const float*)d_in[1];
    const float* inflt = (const float*)d_in[2];
    const float* Wv    = (const float*)d_in[5];
    const float* bv    = (const float*)d_in[6];
    const float* Woff  = (const float*)d_in[7];
    const float* boff  = (const float*)d_in[8];
    const float* Watt  = (const float*)d_in[9];
    const float* batt  = (const float*)d_in[10];
    const float* Wout  = (const float*)d_in[11];
    const float* bout  = (const float*)d_in[12];
    float* out = (float*)d_out;

    __half *qh, *xh, *wv, *wofatt, *wout, *val, *core;
    float *oa;
    cudaGetSymbolAddress((void**)&qh,     g_qh);
    cudaGetSymbolAddress((void**)&xh,     g_xh);
    cudaGetSymbolAddress((void**)&wv,     g_wv);
    cudaGetSymbolAddress((void**)&wofatt, g_wofatt);
    cudaGetSymbolAddress((void**)&wout,   g_wout);
    cudaGetSymbolAddress((void**)&val,    g_val);
    cudaGetSymbolAddress((void**)&oa,     g_oa);
    cudaGetSymbolAddress((void**)&core,   g_core);

    const int SMEM = NSTAGE * STG;   // 80KB dynamic
    cudaFuncSetAttribute(hgemm_fused2_kernel,
                         cudaFuncAttributeMaxDynamicSharedMemorySize, SMEM);
    cudaFuncSetAttribute(hgemm_out_kernel,
                         cudaFuncAttributeMaxDynamicSharedMemorySize, SMEM);

    const int M = MROWS;
    dim3 blk(256);
    const int mb = (M + 127) / 128;   // 279

    // 1. convert everything
    {
        int maxBlocks = (MROWS * 64 + 255) / 256;
        dim3 grid(maxBlocks, 6);
        convert_all_kernel<<<grid, blk>>>(
            (const float4*)inflt, (const float4*)query,
            (const float4*)Wv, (const float4*)Wout,
            (const float4*)Woff, (const float4*)Watt,
            (__half2*)xh, (__half2*)qh, (__half2*)wv, (__half2*)wout,
            (__half2*)wofatt);
    }
    // 2. value GEMM + off|att GEMM fused into one launch
    hgemm_fused2_kernel<<<dim3(5, mb), blk, SMEM>>>(xh, wv, bv, val,
                                                    qh, wofatt, boff, batt, oa);
    // 3. sampling with fused softmax
    {
        int threads = MROWS * HD * 4;
        sample_kernel<<<(threads + 255) / 256, 256>>>(
            refpt, oa, (const uint4*)val, (uint4*)core);
    }
    // 4. out = core @ Wout + bout
    hgemm_out_kernel<<<dim3(2, mb), blk, SMEM>>>(core, wout, bout, out);
}